// round 1
// baseline (speedup 1.0000x reference)
#include <cuda_runtime.h>
#include <math.h>

// Problem constants
#define BB 2
#define SS 2048
#define DD 1024
#define HH 16
#define DHD 64
#define MM (BB*SS)   // 4096

// Scratch (allocation-free rule: __device__ globals)
__device__ float g_qh[BB*HH*SS*DHD];   // [B,H,S,DH] 16 MB
__device__ float g_kh[BB*HH*SS*DHD];
__device__ float g_vh[BB*HH*SS*DHD];
__device__ float g_ao[MM*DD];          // attention out, [B,S,D] 16 MB

// ---------------------------------------------------------------------------
// SGEMM: C = A(M x 1024) @ W(1024 x 1024)^T   (torch Linear semantics)
// Block tile 128x128, K-chunk 16, 256 threads, 8x8 register micro-tile.
// WHICH: 0/1/2 -> write head layout into g_qh/g_kh/g_vh ; 3 -> flat into outp
// ---------------------------------------------------------------------------
template<int WHICH>
__global__ void __launch_bounds__(256) proj_gemm(const float* __restrict__ A,
                                                 const float* __restrict__ W,
                                                 float* __restrict__ outp)
{
    __shared__ float As[16][132];   // A^T tile: As[k][m], pad 132 (2-way max)
    __shared__ float Bs[16][132];   // W^T tile: Bs[k][n]

    const int tid = threadIdx.x;
    const int tx = tid & 15;
    const int ty = tid >> 4;
    const int bm = blockIdx.y * 128;
    const int bn = blockIdx.x * 128;

    float acc[8][8];
    #pragma unroll
    for (int i = 0; i < 8; i++)
        #pragma unroll
        for (int j = 0; j < 8; j++) acc[i][j] = 0.f;

    for (int kt = 0; kt < 1024; kt += 16) {
        #pragma unroll
        for (int u = 0; u < 2; u++) {
            int e  = tid + u * 256;       // 0..511
            int m  = e >> 2;              // 0..127
            int k4 = (e & 3) * 4;         // 0,4,8,12
            float4 va = *(const float4*)(A + (size_t)(bm + m) * 1024 + kt + k4);
            As[k4+0][m] = va.x; As[k4+1][m] = va.y;
            As[k4+2][m] = va.z; As[k4+3][m] = va.w;
            float4 vb = *(const float4*)(W + (size_t)(bn + m) * 1024 + kt + k4);
            Bs[k4+0][m] = vb.x; Bs[k4+1][m] = vb.y;
            Bs[k4+2][m] = vb.z; Bs[k4+3][m] = vb.w;
        }
        __syncthreads();

        #pragma unroll
        for (int kk = 0; kk < 16; kk++) {
            float af[8], bf[8];
            *(float4*)&af[0] = *(const float4*)&As[kk][ty*8];
            *(float4*)&af[4] = *(const float4*)&As[kk][ty*8 + 4];
            *(float4*)&bf[0] = *(const float4*)&Bs[kk][tx*8];
            *(float4*)&bf[4] = *(const float4*)&Bs[kk][tx*8 + 4];
            #pragma unroll
            for (int i = 0; i < 8; i++)
                #pragma unroll
                for (int j = 0; j < 8; j++)
                    acc[i][j] = fmaf(af[i], bf[j], acc[i][j]);
        }
        __syncthreads();
    }

    // Epilogue
    float* dst = nullptr;
    if (WHICH == 0) dst = g_qh;
    else if (WHICH == 1) dst = g_kh;
    else if (WHICH == 2) dst = g_vh;

    #pragma unroll
    for (int i = 0; i < 8; i++) {
        int m = bm + ty * 8 + i;
        #pragma unroll
        for (int jj = 0; jj < 8; jj += 4) {
            int n = bn + tx * 8 + jj;
            float4 o = make_float4(acc[i][jj], acc[i][jj+1], acc[i][jj+2], acc[i][jj+3]);
            if (WHICH == 3) {
                *(float4*)(outp + (size_t)m * 1024 + n) = o;
            } else {
                int b  = m >> 11;      // m / 2048
                int s  = m & 2047;
                int h  = n >> 6;       // head (tx*8 span is 64-aligned-safe: stays in one head)
                int dh = n & 63;
                *(float4*)(dst + (((size_t)(b * HH + h)) * SS + s) * DHD + dh) = o;
            }
        }
    }
}

// ---------------------------------------------------------------------------
// Flash attention (fp32, no mask): per block BM=128 queries x full S keys,
// BN=64 key tile, DH=64. 256 threads, 8x4 micro-tiles for both GEMMs.
// Row ownership: ty (0..15) owns rows ty*8..ty*8+7; tx (0..15) covers 64 cols.
// Row reductions via shfl across the 16-lane tx group.
// ---------------------------------------------------------------------------
#define QLD 132
#define KLD 68

__global__ void __launch_bounds__(256) attn_kernel()
{
    extern __shared__ float sm[];
    float* Qst = sm;                   // [64 d][132 m]  (Q^T, pre-scaled by 1/8)
    float* Kst = Qst + 64 * QLD;       // [64 d][68 n]   (K^T)
    float* Vs  = Kst + 64 * KLD;       // [64 n][68 c]   (V natural)
    float* Ps  = Vs  + 64 * KLD;       // [64 n][132 m]  (P^T)

    const int tid = threadIdx.x;
    const int tx = tid & 15;
    const int ty = tid >> 4;
    const int bh = blockIdx.y;                 // b*H + h, 0..31
    const int m0 = blockIdx.x * 128;

    const float* Qb = g_qh + (size_t)bh * (SS * DHD);
    const float* Kb = g_kh + (size_t)bh * (SS * DHD);
    const float* Vb = g_vh + (size_t)bh * (SS * DHD);

    // Load Q tile transposed, fold in 1/sqrt(64) = 0.125
    #pragma unroll
    for (int u = 0; u < 8; u++) {
        int e  = tid + u * 256;       // 0..2047 float4 units
        int m  = e >> 4;              // 0..127
        int d4 = (e & 15) * 4;        // 0..60
        float4 v = *(const float4*)(Qb + (size_t)(m0 + m) * DHD + d4);
        Qst[(d4+0)*QLD + m] = v.x * 0.125f;
        Qst[(d4+1)*QLD + m] = v.y * 0.125f;
        Qst[(d4+2)*QLD + m] = v.z * 0.125f;
        Qst[(d4+3)*QLD + m] = v.w * 0.125f;
    }

    float mi[8], li[8], oacc[8][4];
    #pragma unroll
    for (int i = 0; i < 8; i++) {
        mi[i] = -1e30f; li[i] = 0.f;
        #pragma unroll
        for (int j = 0; j < 4; j++) oacc[i][j] = 0.f;
    }

    for (int n0 = 0; n0 < SS; n0 += 64) {
        __syncthreads();  // Q stores visible (iter 0); prev PV done before K/V/P rewrite

        // Load K tile (transposed) and V tile (natural)
        #pragma unroll
        for (int u = 0; u < 4; u++) {
            int e  = tid + u * 256;   // 0..1023
            int n  = e >> 4;          // 0..63
            int d4 = (e & 15) * 4;
            float4 kv = *(const float4*)(Kb + (size_t)(n0 + n) * DHD + d4);
            Kst[(d4+0)*KLD + n] = kv.x;
            Kst[(d4+1)*KLD + n] = kv.y;
            Kst[(d4+2)*KLD + n] = kv.z;
            Kst[(d4+3)*KLD + n] = kv.w;
            float4 vv = *(const float4*)(Vb + (size_t)(n0 + n) * DHD + d4);
            *(float4*)&Vs[n * KLD + d4] = vv;
        }
        __syncthreads();

        // Scores: sc[8][4] = (Q/8) @ K^T
        float sc[8][4];
        #pragma unroll
        for (int i = 0; i < 8; i++)
            #pragma unroll
            for (int j = 0; j < 4; j++) sc[i][j] = 0.f;

        #pragma unroll 16
        for (int d = 0; d < 64; d++) {
            float af[8], bf[4];
            *(float4*)&af[0] = *(const float4*)&Qst[d*QLD + ty*8];
            *(float4*)&af[4] = *(const float4*)&Qst[d*QLD + ty*8 + 4];
            *(float4*)&bf[0] = *(const float4*)&Kst[d*KLD + tx*4];
            #pragma unroll
            for (int i = 0; i < 8; i++)
                #pragma unroll
                for (int j = 0; j < 4; j++)
                    sc[i][j] = fmaf(af[i], bf[j], sc[i][j]);
        }

        // Online softmax (row stats across 16-lane tx groups)
        #pragma unroll
        for (int i = 0; i < 8; i++) {
            float rm = fmaxf(fmaxf(sc[i][0], sc[i][1]), fmaxf(sc[i][2], sc[i][3]));
            rm = fmaxf(rm, __shfl_xor_sync(0xffffffffu, rm, 1));
            rm = fmaxf(rm, __shfl_xor_sync(0xffffffffu, rm, 2));
            rm = fmaxf(rm, __shfl_xor_sync(0xffffffffu, rm, 4));
            rm = fmaxf(rm, __shfl_xor_sync(0xffffffffu, rm, 8));
            float mnew  = fmaxf(mi[i], rm);
            float alpha = __expf(mi[i] - mnew);
            mi[i] = mnew;
            float rs = 0.f;
            #pragma unroll
            for (int j = 0; j < 4; j++) {
                sc[i][j] = __expf(sc[i][j] - mnew);
                rs += sc[i][j];
            }
            rs += __shfl_xor_sync(0xffffffffu, rs, 1);
            rs += __shfl_xor_sync(0xffffffffu, rs, 2);
            rs += __shfl_xor_sync(0xffffffffu, rs, 4);
            rs += __shfl_xor_sync(0xffffffffu, rs, 8);
            li[i] = li[i] * alpha + rs;
            #pragma unroll
            for (int j = 0; j < 4; j++) oacc[i][j] *= alpha;
        }

        // Stage P^T to smem: Ps[n][m]
        #pragma unroll
        for (int j = 0; j < 4; j++) {
            int n = tx * 4 + j;
            *(float4*)&Ps[n*QLD + ty*8]     = make_float4(sc[0][j], sc[1][j], sc[2][j], sc[3][j]);
            *(float4*)&Ps[n*QLD + ty*8 + 4] = make_float4(sc[4][j], sc[5][j], sc[6][j], sc[7][j]);
        }
        __syncthreads();

        // O += P @ V
        #pragma unroll 16
        for (int n = 0; n < 64; n++) {
            float af[8], bf[4];
            *(float4*)&af[0] = *(const float4*)&Ps[n*QLD + ty*8];
            *(float4*)&af[4] = *(const float4*)&Ps[n*QLD + ty*8 + 4];
            *(float4*)&bf[0] = *(const float4*)&Vs[n*KLD + tx*4];
            #pragma unroll
            for (int i = 0; i < 8; i++)
                #pragma unroll
                for (int j = 0; j < 4; j++)
                    oacc[i][j] = fmaf(af[i], bf[j], oacc[i][j]);
        }
    }

    // Epilogue: normalize, write concat layout [B,S,D]
    const int b = bh >> 4;   // bh / H
    const int h = bh & 15;
    #pragma unroll
    for (int i = 0; i < 8; i++) {
        float inv = 1.0f / li[i];
        int m = m0 + ty * 8 + i;
        float4 o = make_float4(oacc[i][0]*inv, oacc[i][1]*inv, oacc[i][2]*inv, oacc[i][3]*inv);
        *(float4*)(g_ao + ((size_t)b * SS + m) * DD + h * DHD + tx * 4) = o;
    }
}

#define ATTN_SMEM ((64*QLD + 64*KLD + 64*KLD + 64*QLD) * (int)sizeof(float))  // 102400 B

extern "C" void kernel_launch(void* const* d_in, const int* in_sizes, int n_in,
                              void* d_out, int out_size)
{
    const float* q  = (const float*)d_in[0];
    const float* k  = (const float*)d_in[1];
    const float* v  = (const float*)d_in[2];
    const float* Wq = (const float*)d_in[3];
    const float* Wk = (const float*)d_in[4];
    const float* Wv = (const float*)d_in[5];
    const float* Wo = (const float*)d_in[6];
    float* out = (float*)d_out;

    dim3 gg(1024/128, MM/128);   // (8, 32)
    dim3 bb(256);

    proj_gemm<0><<<gg, bb>>>(q, Wq, nullptr);
    proj_gemm<1><<<gg, bb>>>(k, Wk, nullptr);
    proj_gemm<2><<<gg, bb>>>(v, Wv, nullptr);

    cudaFuncSetAttribute(attn_kernel,
                         cudaFuncAttributeMaxDynamicSharedMemorySize, ATTN_SMEM);
    dim3 ga(SS/128, BB*HH);      // (16, 32)
    attn_kernel<<<ga, bb, ATTN_SMEM>>>();

    // ao is fully written by attn grid before this (same stream)
    float* ao_ptr = nullptr;     // final GEMM reads g_ao via template path? No:
    // WHICH=3 reads A from param; pass g_ao via a device-symbol-free trick:
    // use a tiny kernel-side alias by launching with A = address of g_ao is not
    // available on host without cudaGetSymbolAddress — which is a benign,
    // non-stream, non-allocating call:
    cudaGetSymbolAddress((void**)&ao_ptr, g_ao);
    proj_gemm<3><<<gg, bb>>>(ao_ptr, Wo, out);
}

// round 3
// speedup vs baseline: 1.3560x; 1.3560x over previous
#include <cuda_runtime.h>
#include <cuda_bf16.h>
#include <cstdint>
#include <math.h>

// ---------------- problem constants ----------------
#define BB 2
#define SS 2048
#define DD 1024
#define HH 16
#define DHD 64
#define MM (BB*SS)      // 4096

// ---------------- split-bf16 GEMM constants ----------------
#define KTOT 3072       // stacked K' = 3 x 1024
#define MB 128          // CTA M tile
#define NB 128          // CTA N tile
#define KC 32           // bf16 K per chunk (64 B rows)
#define NCHUNK (KTOT/KC)        // 96
#define NSTG 4
#define A_STG 8192              // 128 rows x 64 B
#define B_STG 8192
#define STG_BYTES (A_STG+B_STG) // 16384
#define GEMM_SMEM (NSTG*STG_BYTES)  // 65536

// ---------------- scratch (__device__ globals; no allocs allowed) ----------
__device__ float g_qh[BB*HH*SS*DHD];
__device__ float g_kh[BB*HH*SS*DHD];
__device__ float g_vh[BB*HH*SS*DHD];
__device__ float g_ao[MM*DD];

__device__ __nv_bfloat16 g_q3[(size_t)MM*KTOT];
__device__ __nv_bfloat16 g_k3[(size_t)MM*KTOT];
__device__ __nv_bfloat16 g_v3[(size_t)MM*KTOT];
__device__ __nv_bfloat16 g_o3[(size_t)MM*KTOT];
__device__ __nv_bfloat16 g_wq3[(size_t)DD*KTOT];
__device__ __nv_bfloat16 g_wk3[(size_t)DD*KTOT];
__device__ __nv_bfloat16 g_wv3[(size_t)DD*KTOT];
__device__ __nv_bfloat16 g_wo3[(size_t)DD*KTOT];

// ---------------- PTX helpers (sm_100-safe: cp.async / ldmatrix / mma.sync) --
__device__ __forceinline__ uint32_t smem_u32(const void* p) {
    uint32_t a;
    asm("{ .reg .u64 t; cvta.to.shared.u64 t, %1; cvt.u32.u64 %0, t; }"
        : "=r"(a) : "l"(p));
    return a;
}

#define CP_ASYNC16(dst, src) \
    asm volatile("cp.async.cg.shared.global [%0], [%1], 16;" :: "r"(dst), "l"(src))
#define CP_COMMIT() asm volatile("cp.async.commit_group;" ::: "memory")
#define CP_WAIT2()  asm volatile("cp.async.wait_group 2;" ::: "memory")

#define LDSM4(r0, r1, r2, r3, addr) \
    asm volatile("ldmatrix.sync.aligned.m8n8.x4.shared.b16 {%0,%1,%2,%3}, [%4];" \
        : "=r"(r0), "=r"(r1), "=r"(r2), "=r"(r3) : "r"(addr))

#define MMA16816(c, a, b) \
    asm volatile("mma.sync.aligned.m16n8k16.row.col.f32.bf16.bf16.f32 " \
        "{%0,%1,%2,%3}, {%4,%5,%6,%7}, {%8,%9}, {%0,%1,%2,%3};" \
        : "+f"((c)[0]), "+f"((c)[1]), "+f"((c)[2]), "+f"((c)[3]) \
        : "r"((a)[0]), "r"((a)[1]), "r"((a)[2]), "r"((a)[3]), \
          "r"((b)[0]), "r"((b)[1]))

// swizzled byte offset within an [rows][32 bf16] tile (64 B rows, 16 B granules)
__device__ __forceinline__ uint32_t swz(int row, int g) {
    return (uint32_t)(row * 64 + ((g ^ ((row >> 1) & 3)) * 16));
}

// ---------------------------------------------------------------------------
// split3: fp32 [rows,1024] -> stacked bf16 [rows,3072]
//   act == 1 : [hi | lo | hi]  (activations)    act == 0 : [hi | hi | lo]
// ---------------------------------------------------------------------------
__global__ void __launch_bounds__(256) split3(const float4* __restrict__ X,
                                              __nv_bfloat16* __restrict__ Y,
                                              int act)
{
    int e = blockIdx.x * 256 + threadIdx.x;   // float4 index
    int row = e >> 8;
    int c4  = e & 255;
    float4 x = X[e];

    __nv_bfloat162 ha = __floats2bfloat162_rn(x.x, x.y);
    __nv_bfloat162 hb = __floats2bfloat162_rn(x.z, x.w);
    __nv_bfloat162 la = __floats2bfloat162_rn(x.x - __low2float(ha), x.y - __high2float(ha));
    __nv_bfloat162 lb = __floats2bfloat162_rn(x.z - __low2float(hb), x.w - __high2float(hb));

    __nv_bfloat162* y  = (__nv_bfloat162*)(Y + (size_t)row * KTOT + c4 * 4);
    __nv_bfloat162* y1 = y + 512;     // +1024 elems
    __nv_bfloat162* y2 = y + 1024;    // +2048 elems
    y[0] = ha; y[1] = hb;
    if (act) { y1[0] = la; y1[1] = lb; y2[0] = ha; y2[1] = hb; }
    else     { y1[0] = ha; y1[1] = hb; y2[0] = la; y2[1] = lb; }
}

// ---------------------------------------------------------------------------
// warp-MMA GEMM: C[m,n] = A3[M,3072] @ W3[N,3072]^T  (bf16 in, f32 out)
// CTA 128x128, 8 warps (2M x 4N), warp tile 64x32, mma.sync m16n8k16.
// headlayout!=0 -> scatter C into [B,H,S,DH]; else flat [m, 1024].
// ---------------------------------------------------------------------------
__global__ void __launch_bounds__(256) gemm_mma(const __nv_bfloat16* __restrict__ A3,
                                                const __nv_bfloat16* __restrict__ W3,
                                                float* __restrict__ dstp,
                                                int headlayout)
{
    extern __shared__ char dsm[];
    const uint32_t sb = smem_u32(dsm);

    const int tid  = threadIdx.x;
    const int lane = tid & 31;
    const int wid  = tid >> 5;
    const int wm   = (wid & 1) * 64;      // warp M base within CTA
    const int wn   = (wid >> 1) * 32;     // warp N base within CTA
    const int bm   = blockIdx.y * MB;
    const int bn   = blockIdx.x * NB;

    const char* gA = (const char*)(A3 + (size_t)bm * KTOT);
    const char* gB = (const char*)(W3 + (size_t)bn * KTOT);

    float cfr[4][4][4];
    #pragma unroll
    for (int i = 0; i < 4; i++)
        #pragma unroll
        for (int j = 0; j < 4; j++)
            #pragma unroll
            for (int e = 0; e < 4; e++) cfr[i][j][e] = 0.f;

    // per-thread load slots: 4 granules per stage (1024 granules / 256 thr)
    // G = tid + i*256 ; G<512 -> A tile, else B tile
    int l_isB[4], l_row[4];
    uint32_t l_soff[4];
    size_t l_goff[4];
    #pragma unroll
    for (int i = 0; i < 4; i++) {
        int G = tid + i * 256;
        l_isB[i] = G >> 9;
        int g = G & 511;
        l_row[i] = g >> 2;
        int q = g & 3;
        l_soff[i] = (l_isB[i] ? A_STG : 0u) + swz(l_row[i], q);
        l_goff[i] = (size_t)l_row[i] * (KTOT * 2) + q * 16;
    }

    // prefetch stages 0..2
    #pragma unroll
    for (int s = 0; s < NSTG - 1; s++) {
        const uint32_t st = sb + s * STG_BYTES;
        #pragma unroll
        for (int i = 0; i < 4; i++) {
            const char* src = (l_isB[i] ? gB : gA) + l_goff[i] + (size_t)s * (KC * 2);
            CP_ASYNC16(st + l_soff[i], src);
        }
        CP_COMMIT();
    }

    // ldmatrix lane addressing (constant across chunks except kg/stage)
    const int a_row = lane & 15;          // row within m-tile
    const int a_kg  = lane >> 4;          // k-granule half (0/1)
    const int b_j   = lane >> 4;          // n-tile within pair
    const int b_half= (lane >> 3) & 1;    // k-granule half
    const int b_row = lane & 7;           // row within n-tile

    #pragma unroll 1
    for (int c = 0; c < NCHUNK; c++) {
        CP_WAIT2();
        __syncthreads();

        // issue loads for stage c+3
        if (c + NSTG - 1 < NCHUNK) {
            const uint32_t st = sb + ((c + NSTG - 1) & (NSTG - 1)) * STG_BYTES;
            #pragma unroll
            for (int i = 0; i < 4; i++) {
                const char* src = (l_isB[i] ? gB : gA) + l_goff[i]
                                + (size_t)(c + NSTG - 1) * (KC * 2);
                CP_ASYNC16(st + l_soff[i], src);
            }
        }
        CP_COMMIT();

        const uint32_t sA = sb + (c & (NSTG - 1)) * STG_BYTES;
        const uint32_t sBs = sA + A_STG;

        #pragma unroll
        for (int ks = 0; ks < 2; ks++) {
            uint32_t a[4][4];
            #pragma unroll
            for (int mt = 0; mt < 4; mt++) {
                int row = wm + mt * 16 + a_row;
                int kg  = ks * 2 + a_kg;
                LDSM4(a[mt][0], a[mt][1], a[mt][2], a[mt][3], sA + swz(row, kg));
            }
            uint32_t b[4][2];
            #pragma unroll
            for (int pr = 0; pr < 2; pr++) {
                int row = wn + (pr * 2 + b_j) * 8 + b_row;
                int kg  = ks * 2 + b_half;
                uint32_t r0, r1, r2, r3;
                LDSM4(r0, r1, r2, r3, sBs + swz(row, kg));
                b[pr*2][0] = r0; b[pr*2][1] = r1;
                b[pr*2+1][0] = r2; b[pr*2+1][1] = r3;
            }
            #pragma unroll
            for (int mt = 0; mt < 4; mt++)
                #pragma unroll
                for (int nt = 0; nt < 4; nt++)
                    MMA16816(cfr[mt][nt], a[mt], b[nt]);
        }
        __syncthreads();
    }

    // epilogue: lane holds rows (lane>>2, +8), cols (lane&3)*2 per (mt,nt)
    const int r0 = lane >> 2;
    const int cc0 = (lane & 3) * 2;
    #pragma unroll
    for (int mt = 0; mt < 4; mt++) {
        #pragma unroll
        for (int nt = 0; nt < 4; nt++) {
            int m = bm + wm + mt * 16 + r0;
            int n = bn + wn + nt * 8 + cc0;
            float* d0;
            if (headlayout) {
                int bb = m >> 11, s = m & 2047, h = n >> 6, dh = n & 63;
                d0 = dstp + (((size_t)(bb * HH + h) * SS + s) * DHD + dh);
                float2 v0 = make_float2(cfr[mt][nt][0], cfr[mt][nt][1]);
                float2 v1 = make_float2(cfr[mt][nt][2], cfr[mt][nt][3]);
                *(float2*)d0 = v0;
                *(float2*)(d0 + 8 * DHD) = v1;   // row +8 within same head
            } else {
                d0 = dstp + (size_t)m * DD + n;
                *(float2*)d0 = make_float2(cfr[mt][nt][0], cfr[mt][nt][1]);
                *(float2*)(d0 + 8 * DD) = make_float2(cfr[mt][nt][2], cfr[mt][nt][3]);
            }
        }
    }
}

// ---------------------------------------------------------------------------
// Flash attention (fp32) — unchanged verified Round-1 kernel
// ---------------------------------------------------------------------------
#define QLD 132
#define KLD 68

__global__ void __launch_bounds__(256) attn_kernel()
{
    extern __shared__ float sm[];
    float* Qst = sm;
    float* Kst = Qst + 64 * QLD;
    float* Vs  = Kst + 64 * KLD;
    float* Ps  = Vs  + 64 * KLD;

    const int tid = threadIdx.x;
    const int tx = tid & 15;
    const int ty = tid >> 4;
    const int bh = blockIdx.y;
    const int m0 = blockIdx.x * 128;

    const float* Qb = g_qh + (size_t)bh * (SS * DHD);
    const float* Kb = g_kh + (size_t)bh * (SS * DHD);
    const float* Vb = g_vh + (size_t)bh * (SS * DHD);

    #pragma unroll
    for (int u = 0; u < 8; u++) {
        int e  = tid + u * 256;
        int m  = e >> 4;
        int d4 = (e & 15) * 4;
        float4 v = *(const float4*)(Qb + (size_t)(m0 + m) * DHD + d4);
        Qst[(d4+0)*QLD + m] = v.x * 0.125f;
        Qst[(d4+1)*QLD + m] = v.y * 0.125f;
        Qst[(d4+2)*QLD + m] = v.z * 0.125f;
        Qst[(d4+3)*QLD + m] = v.w * 0.125f;
    }

    float mi[8], li[8], oacc[8][4];
    #pragma unroll
    for (int i = 0; i < 8; i++) {
        mi[i] = -1e30f; li[i] = 0.f;
        #pragma unroll
        for (int j = 0; j < 4; j++) oacc[i][j] = 0.f;
    }

    for (int n0 = 0; n0 < SS; n0 += 64) {
        __syncthreads();

        #pragma unroll
        for (int u = 0; u < 4; u++) {
            int e  = tid + u * 256;
            int n  = e >> 4;
            int d4 = (e & 15) * 4;
            float4 kv = *(const float4*)(Kb + (size_t)(n0 + n) * DHD + d4);
            Kst[(d4+0)*KLD + n] = kv.x;
            Kst[(d4+1)*KLD + n] = kv.y;
            Kst[(d4+2)*KLD + n] = kv.z;
            Kst[(d4+3)*KLD + n] = kv.w;
            float4 vv = *(const float4*)(Vb + (size_t)(n0 + n) * DHD + d4);
            *(float4*)&Vs[n * KLD + d4] = vv;
        }
        __syncthreads();

        float sc[8][4];
        #pragma unroll
        for (int i = 0; i < 8; i++)
            #pragma unroll
            for (int j = 0; j < 4; j++) sc[i][j] = 0.f;

        #pragma unroll 16
        for (int d = 0; d < 64; d++) {
            float af[8], bf[4];
            *(float4*)&af[0] = *(const float4*)&Qst[d*QLD + ty*8];
            *(float4*)&af[4] = *(const float4*)&Qst[d*QLD + ty*8 + 4];
            *(float4*)&bf[0] = *(const float4*)&Kst[d*KLD + tx*4];
            #pragma unroll
            for (int i = 0; i < 8; i++)
                #pragma unroll
                for (int j = 0; j < 4; j++)
                    sc[i][j] = fmaf(af[i], bf[j], sc[i][j]);
        }

        #pragma unroll
        for (int i = 0; i < 8; i++) {
            float rm = fmaxf(fmaxf(sc[i][0], sc[i][1]), fmaxf(sc[i][2], sc[i][3]));
            rm = fmaxf(rm, __shfl_xor_sync(0xffffffffu, rm, 1));
            rm = fmaxf(rm, __shfl_xor_sync(0xffffffffu, rm, 2));
            rm = fmaxf(rm, __shfl_xor_sync(0xffffffffu, rm, 4));
            rm = fmaxf(rm, __shfl_xor_sync(0xffffffffu, rm, 8));
            float mnew  = fmaxf(mi[i], rm);
            float alpha = __expf(mi[i] - mnew);
            mi[i] = mnew;
            float rs = 0.f;
            #pragma unroll
            for (int j = 0; j < 4; j++) {
                sc[i][j] = __expf(sc[i][j] - mnew);
                rs += sc[i][j];
            }
            rs += __shfl_xor_sync(0xffffffffu, rs, 1);
            rs += __shfl_xor_sync(0xffffffffu, rs, 2);
            rs += __shfl_xor_sync(0xffffffffu, rs, 4);
            rs += __shfl_xor_sync(0xffffffffu, rs, 8);
            li[i] = li[i] * alpha + rs;
            #pragma unroll
            for (int j = 0; j < 4; j++) oacc[i][j] *= alpha;
        }

        #pragma unroll
        for (int j = 0; j < 4; j++) {
            int n = tx * 4 + j;
            *(float4*)&Ps[n*QLD + ty*8]     = make_float4(sc[0][j], sc[1][j], sc[2][j], sc[3][j]);
            *(float4*)&Ps[n*QLD + ty*8 + 4] = make_float4(sc[4][j], sc[5][j], sc[6][j], sc[7][j]);
        }
        __syncthreads();

        #pragma unroll 16
        for (int n = 0; n < 64; n++) {
            float af[8], bf[4];
            *(float4*)&af[0] = *(const float4*)&Ps[n*QLD + ty*8];
            *(float4*)&af[4] = *(const float4*)&Ps[n*QLD + ty*8 + 4];
            *(float4*)&bf[0] = *(const float4*)&Vs[n*KLD + tx*4];
            #pragma unroll
            for (int i = 0; i < 8; i++)
                #pragma unroll
                for (int j = 0; j < 4; j++)
                    oacc[i][j] = fmaf(af[i], bf[j], oacc[i][j]);
        }
    }

    const int b = bh >> 4;
    const int h = bh & 15;
    #pragma unroll
    for (int i = 0; i < 8; i++) {
        float inv = 1.0f / li[i];
        int m = m0 + ty * 8 + i;
        float4 o = make_float4(oacc[i][0]*inv, oacc[i][1]*inv, oacc[i][2]*inv, oacc[i][3]*inv);
        *(float4*)(g_ao + ((size_t)b * SS + m) * DD + h * DHD + tx * 4) = o;
    }
}

#define ATTN_SMEM ((64*QLD + 64*KLD + 64*KLD + 64*QLD) * (int)sizeof(float))

// ---------------------------------------------------------------------------
extern "C" void kernel_launch(void* const* d_in, const int* in_sizes, int n_in,
                              void* d_out, int out_size)
{
    const float* q  = (const float*)d_in[0];
    const float* k  = (const float*)d_in[1];
    const float* v  = (const float*)d_in[2];
    const float* Wq = (const float*)d_in[3];
    const float* Wk = (const float*)d_in[4];
    const float* Wv = (const float*)d_in[5];
    const float* Wo = (const float*)d_in[6];
    float* out = (float*)d_out;

    __nv_bfloat16 *q3, *k3, *v3, *o3, *wq3, *wk3, *wv3, *wo3;
    float *qh, *kh, *vh, *ao;
    cudaGetSymbolAddress((void**)&q3,  g_q3);
    cudaGetSymbolAddress((void**)&k3,  g_k3);
    cudaGetSymbolAddress((void**)&v3,  g_v3);
    cudaGetSymbolAddress((void**)&o3,  g_o3);
    cudaGetSymbolAddress((void**)&wq3, g_wq3);
    cudaGetSymbolAddress((void**)&wk3, g_wk3);
    cudaGetSymbolAddress((void**)&wv3, g_wv3);
    cudaGetSymbolAddress((void**)&wo3, g_wo3);
    cudaGetSymbolAddress((void**)&qh,  g_qh);
    cudaGetSymbolAddress((void**)&kh,  g_kh);
    cudaGetSymbolAddress((void**)&vh,  g_vh);
    cudaGetSymbolAddress((void**)&ao,  g_ao);

    cudaFuncSetAttribute(gemm_mma, cudaFuncAttributeMaxDynamicSharedMemorySize, GEMM_SMEM);
    cudaFuncSetAttribute(attn_kernel, cudaFuncAttributeMaxDynamicSharedMemorySize, ATTN_SMEM);

    // split fp32 -> stacked bf16
    split3<<<MM, 256>>>((const float4*)q,  q3, 1);
    split3<<<MM, 256>>>((const float4*)k,  k3, 1);
    split3<<<MM, 256>>>((const float4*)v,  v3, 1);
    split3<<<DD, 256>>>((const float4*)Wq, wq3, 0);
    split3<<<DD, 256>>>((const float4*)Wk, wk3, 0);
    split3<<<DD, 256>>>((const float4*)Wv, wv3, 0);
    split3<<<DD, 256>>>((const float4*)Wo, wo3, 0);

    // projections on tensor cores (write head layout)
    dim3 gg(DD / NB, MM / MB);   // (8, 32)
    gemm_mma<<<gg, 256, GEMM_SMEM>>>(q3, wq3, qh, 1);
    gemm_mma<<<gg, 256, GEMM_SMEM>>>(k3, wk3, kh, 1);
    gemm_mma<<<gg, 256, GEMM_SMEM>>>(v3, wv3, vh, 1);

    // fp32 flash attention
    dim3 ga(SS / 128, BB * HH);
    attn_kernel<<<ga, 256, ATTN_SMEM>>>();

    // output projection
    split3<<<MM, 256>>>((const float4*)ao, o3, 1);
    gemm_mma<<<gg, 256, GEMM_SMEM>>>(o3, wo3, out, 0);
}

// round 4
// speedup vs baseline: 3.3889x; 2.4992x over previous
#include <cuda_runtime.h>
#include <cuda_bf16.h>
#include <cuda_fp16.h>
#include <cstdint>
#include <math.h>

// ---------------- problem constants ----------------
#define BB 2
#define SS 2048
#define DD 1024
#define HH 16
#define DHD 64
#define MM (BB*SS)      // 4096

// ---------------- split-bf16 GEMM constants ----------------
#define KTOT 3072
#define MB 128
#define NB 128
#define KC 32
#define NCHUNK (KTOT/KC)        // 96
#define NSTG 4
#define A_STG 8192
#define B_STG 8192
#define STG_BYTES (A_STG+B_STG)
#define GEMM_SMEM (NSTG*STG_BYTES)  // 65536

// ---------------- scratch ----------------
__device__ float g_ao[MM*DD];
__device__ __half g_qh16[BB*HH*SS*DHD];
__device__ __half g_kh16[BB*HH*SS*DHD];
__device__ __half g_vh16[BB*HH*SS*DHD];

__device__ __nv_bfloat16 g_q3[(size_t)MM*KTOT];
__device__ __nv_bfloat16 g_k3[(size_t)MM*KTOT];
__device__ __nv_bfloat16 g_v3[(size_t)MM*KTOT];
__device__ __nv_bfloat16 g_o3[(size_t)MM*KTOT];
__device__ __nv_bfloat16 g_wq3[(size_t)DD*KTOT];
__device__ __nv_bfloat16 g_wk3[(size_t)DD*KTOT];
__device__ __nv_bfloat16 g_wv3[(size_t)DD*KTOT];
__device__ __nv_bfloat16 g_wo3[(size_t)DD*KTOT];

// ---------------- PTX helpers ----------------
__device__ __forceinline__ uint32_t smem_u32(const void* p) {
    uint32_t a;
    asm("{ .reg .u64 t; cvta.to.shared.u64 t, %1; cvt.u32.u64 %0, t; }"
        : "=r"(a) : "l"(p));
    return a;
}

#define CP_ASYNC16(dst, src) \
    asm volatile("cp.async.cg.shared.global [%0], [%1], 16;" :: "r"(dst), "l"(src))
#define CP_COMMIT() asm volatile("cp.async.commit_group;" ::: "memory")
#define CP_WAIT2()  asm volatile("cp.async.wait_group 2;" ::: "memory")

#define LDSM4(r0, r1, r2, r3, addr) \
    asm volatile("ldmatrix.sync.aligned.m8n8.x4.shared.b16 {%0,%1,%2,%3}, [%4];" \
        : "=r"(r0), "=r"(r1), "=r"(r2), "=r"(r3) : "r"(addr))
#define LDSM4T(r0, r1, r2, r3, addr) \
    asm volatile("ldmatrix.sync.aligned.m8n8.x4.trans.shared.b16 {%0,%1,%2,%3}, [%4];" \
        : "=r"(r0), "=r"(r1), "=r"(r2), "=r"(r3) : "r"(addr))

#define MMABF(c, a, b) \
    asm volatile("mma.sync.aligned.m16n8k16.row.col.f32.bf16.bf16.f32 " \
        "{%0,%1,%2,%3}, {%4,%5,%6,%7}, {%8,%9}, {%0,%1,%2,%3};" \
        : "+f"((c)[0]), "+f"((c)[1]), "+f"((c)[2]), "+f"((c)[3]) \
        : "r"((a)[0]), "r"((a)[1]), "r"((a)[2]), "r"((a)[3]), \
          "r"((b)[0]), "r"((b)[1]))

#define MMAFP16(c, a0, a1, a2, a3, b0, b1) \
    asm volatile("mma.sync.aligned.m16n8k16.row.col.f32.f16.f16.f32 " \
        "{%0,%1,%2,%3}, {%4,%5,%6,%7}, {%8,%9}, {%0,%1,%2,%3};" \
        : "+f"((c)[0]), "+f"((c)[1]), "+f"((c)[2]), "+f"((c)[3]) \
        : "r"(a0), "r"(a1), "r"(a2), "r"(a3), "r"(b0), "r"(b1))

__device__ __forceinline__ float ex2f(float x) {
    float y; asm("ex2.approx.f32 %0, %1;" : "=f"(y) : "f"(x)); return y;
}

// swizzle for 64B rows (gemm tiles)
__device__ __forceinline__ uint32_t swz(int row, int g) {
    return (uint32_t)(row * 64 + ((g ^ ((row >> 1) & 3)) * 16));
}
// swizzle for 128B rows (attention tiles, 8 granules)
__device__ __forceinline__ uint32_t swz8(int row, int g) {
    return (uint32_t)(row * 128 + ((g ^ (row & 7)) << 4));
}

// ---------------------------------------------------------------------------
// split3: fp32 [rows,1024] -> stacked bf16 [rows,3072]
// ---------------------------------------------------------------------------
__global__ void __launch_bounds__(256) split3(const float4* __restrict__ X,
                                              __nv_bfloat16* __restrict__ Y,
                                              int act)
{
    int e = blockIdx.x * 256 + threadIdx.x;
    int row = e >> 8;
    int c4  = e & 255;
    float4 x = X[e];

    __nv_bfloat162 ha = __floats2bfloat162_rn(x.x, x.y);
    __nv_bfloat162 hb = __floats2bfloat162_rn(x.z, x.w);
    __nv_bfloat162 la = __floats2bfloat162_rn(x.x - __low2float(ha), x.y - __high2float(ha));
    __nv_bfloat162 lb = __floats2bfloat162_rn(x.z - __low2float(hb), x.w - __high2float(hb));

    __nv_bfloat162* y  = (__nv_bfloat162*)(Y + (size_t)row * KTOT + c4 * 4);
    __nv_bfloat162* y1 = y + 512;
    __nv_bfloat162* y2 = y + 1024;
    y[0] = ha; y[1] = hb;
    if (act) { y1[0] = la; y1[1] = lb; y2[0] = ha; y2[1] = hb; }
    else     { y1[0] = ha; y1[1] = hb; y2[0] = la; y2[1] = lb; }
}

// ---------------------------------------------------------------------------
// warp-MMA GEMM (verified R3 core). mode 0: f32 flat out. mode 1: fp16
// head-layout out with scale.
// ---------------------------------------------------------------------------
__global__ void __launch_bounds__(256) gemm_mma(const __nv_bfloat16* __restrict__ A3,
                                                const __nv_bfloat16* __restrict__ W3,
                                                float* __restrict__ f32dst,
                                                __half* __restrict__ h16dst,
                                                float scale, int mode)
{
    extern __shared__ char dsm[];
    const uint32_t sb = smem_u32(dsm);

    const int tid  = threadIdx.x;
    const int lane = tid & 31;
    const int wid  = tid >> 5;
    const int wm   = (wid & 1) * 64;
    const int wn   = (wid >> 1) * 32;
    const int bm   = blockIdx.y * MB;
    const int bn   = blockIdx.x * NB;

    const char* gA = (const char*)(A3 + (size_t)bm * KTOT);
    const char* gB = (const char*)(W3 + (size_t)bn * KTOT);

    float cfr[4][4][4];
    #pragma unroll
    for (int i = 0; i < 4; i++)
        #pragma unroll
        for (int j = 0; j < 4; j++)
            #pragma unroll
            for (int e = 0; e < 4; e++) cfr[i][j][e] = 0.f;

    int l_isB[4];
    uint32_t l_soff[4];
    size_t l_goff[4];
    #pragma unroll
    for (int i = 0; i < 4; i++) {
        int G = tid + i * 256;
        l_isB[i] = G >> 9;
        int g = G & 511;
        int row = g >> 2;
        int q = g & 3;
        l_soff[i] = (l_isB[i] ? A_STG : 0u) + swz(row, q);
        l_goff[i] = (size_t)row * (KTOT * 2) + q * 16;
    }

    #pragma unroll
    for (int s = 0; s < NSTG - 1; s++) {
        const uint32_t st = sb + s * STG_BYTES;
        #pragma unroll
        for (int i = 0; i < 4; i++) {
            const char* src = (l_isB[i] ? gB : gA) + l_goff[i] + (size_t)s * (KC * 2);
            CP_ASYNC16(st + l_soff[i], src);
        }
        CP_COMMIT();
    }

    const int a_row = lane & 15;
    const int a_kg  = lane >> 4;
    const int b_j   = lane >> 4;
    const int b_half= (lane >> 3) & 1;
    const int b_row = lane & 7;

    #pragma unroll 1
    for (int c = 0; c < NCHUNK; c++) {
        CP_WAIT2();
        __syncthreads();

        if (c + NSTG - 1 < NCHUNK) {
            const uint32_t st = sb + ((c + NSTG - 1) & (NSTG - 1)) * STG_BYTES;
            #pragma unroll
            for (int i = 0; i < 4; i++) {
                const char* src = (l_isB[i] ? gB : gA) + l_goff[i]
                                + (size_t)(c + NSTG - 1) * (KC * 2);
                CP_ASYNC16(st + l_soff[i], src);
            }
        }
        CP_COMMIT();

        const uint32_t sA = sb + (c & (NSTG - 1)) * STG_BYTES;
        const uint32_t sBs = sA + A_STG;

        #pragma unroll
        for (int ks = 0; ks < 2; ks++) {
            uint32_t a[4][4];
            #pragma unroll
            for (int mt = 0; mt < 4; mt++) {
                int row = wm + mt * 16 + a_row;
                int kg  = ks * 2 + a_kg;
                LDSM4(a[mt][0], a[mt][1], a[mt][2], a[mt][3], sA + swz(row, kg));
            }
            uint32_t b[4][2];
            #pragma unroll
            for (int pr = 0; pr < 2; pr++) {
                int row = wn + (pr * 2 + b_j) * 8 + b_row;
                int kg  = ks * 2 + b_half;
                uint32_t r0, r1, r2, r3;
                LDSM4(r0, r1, r2, r3, sBs + swz(row, kg));
                b[pr*2][0] = r0; b[pr*2][1] = r1;
                b[pr*2+1][0] = r2; b[pr*2+1][1] = r3;
            }
            #pragma unroll
            for (int mt = 0; mt < 4; mt++)
                #pragma unroll
                for (int nt = 0; nt < 4; nt++)
                    MMABF(cfr[mt][nt], a[mt], b[nt]);
        }
        __syncthreads();
    }

    const int r0 = lane >> 2;
    const int cc0 = (lane & 3) * 2;
    #pragma unroll
    for (int mt = 0; mt < 4; mt++) {
        #pragma unroll
        for (int nt = 0; nt < 4; nt++) {
            int m = bm + wm + mt * 16 + r0;
            int n = bn + wn + nt * 8 + cc0;
            if (mode == 1) {
                int bb = m >> 11, s = m & 2047, h = n >> 6, dh = n & 63;
                __half* d0 = h16dst + (((size_t)(bb * HH + h) * SS + s) * DHD + dh);
                *(__half2*)d0 = __floats2half2_rn(cfr[mt][nt][0]*scale, cfr[mt][nt][1]*scale);
                *(__half2*)(d0 + 8 * DHD) = __floats2half2_rn(cfr[mt][nt][2]*scale, cfr[mt][nt][3]*scale);
            } else {
                float* d0 = f32dst + (size_t)m * DD + n;
                *(float2*)d0 = make_float2(cfr[mt][nt][0], cfr[mt][nt][1]);
                *(float2*)(d0 + 8 * DD) = make_float2(cfr[mt][nt][2], cfr[mt][nt][3]);
            }
        }
    }
}

// ---------------------------------------------------------------------------
// Tensor-core flash attention (fp16 mma.sync, fp32 accum, exp2 domain).
// CTA: 128 queries x full S. 8 warps, each owns 16 rows. 64-key tiles.
// smem: Q[128x64 fp16] + 3 stages of (K tile + V tile) = 64 KB.
// ---------------------------------------------------------------------------
#define AT_NIT (SS/64)          // 32
#define AT_KV_STG 16384         // 8KB K + 8KB V
#define ATTN_SMEM (16384 + 3*AT_KV_STG)   // 65536

__global__ void __launch_bounds__(256) attn_mma()
{
    extern __shared__ char smA[];
    const uint32_t sQ  = smem_u32(smA);
    const uint32_t sKV = sQ + 16384;

    const int tid  = threadIdx.x;
    const int lane = tid & 31;
    const int wrp  = tid >> 5;
    const int bh   = blockIdx.y;
    const int qm0  = blockIdx.x * 128;

    const char* Qg = (const char*)g_qh16 + ((size_t)bh * SS + qm0) * 128;
    const char* Kg = (const char*)g_kh16 + (size_t)bh * SS * 128;
    const char* Vg = (const char*)g_vh16 + (size_t)bh * SS * 128;

    // per-thread KV load slots (1024 granules / 256 threads = 4)
    int kv_isV[4], kv_row[4], kv_g[4];
    #pragma unroll
    for (int i = 0; i < 4; i++) {
        int G = tid + i * 256;
        kv_isV[i] = G >> 9;
        int g = G & 511;
        kv_row[i] = g >> 3;
        kv_g[i]   = g & 7;
    }

    // prologue: group0 = Q + KV tile0, group1 = KV tile1
    #pragma unroll
    for (int i = 0; i < 4; i++) {
        int G = tid + i * 256;
        int r = G >> 3, g = G & 7;
        CP_ASYNC16(sQ + swz8(r, g), Qg + r * 128 + g * 16);
    }
    #pragma unroll
    for (int i = 0; i < 4; i++) {
        uint32_t dst = sKV + (kv_isV[i] ? 8192u : 0u) + swz8(kv_row[i], kv_g[i]);
        const char* src = (kv_isV[i] ? Vg : Kg) + (size_t)kv_row[i] * 128 + kv_g[i] * 16;
        CP_ASYNC16(dst, src);
    }
    CP_COMMIT();
    #pragma unroll
    for (int i = 0; i < 4; i++) {
        uint32_t dst = sKV + AT_KV_STG + (kv_isV[i] ? 8192u : 0u) + swz8(kv_row[i], kv_g[i]);
        const char* src = (kv_isV[i] ? Vg : Kg) + (size_t)(64 + kv_row[i]) * 128 + kv_g[i] * 16;
        CP_ASYNC16(dst, src);
    }
    CP_COMMIT();

    uint32_t qa[4][4];          // Q a-frags, loop-invariant
    float oacc[8][4];
    #pragma unroll
    for (int nt = 0; nt < 8; nt++)
        #pragma unroll
        for (int j = 0; j < 4; j++) oacc[nt][j] = 0.f;
    float mi0 = -1e30f, mi1 = -1e30f, li0 = 0.f, li1 = 0.f;

    // ldmatrix lane constants
    const int aq_row = wrp * 16 + (lane & 15);
    const int aq_kg  = lane >> 4;
    const int kb_sub = lane >> 4;            // ntile within pair
    const int kb_half = (lane >> 3) & 1;     // k-granule half
    const int kb_row = lane & 7;
    const int vb_rsub = (lane >> 3) & 1;     // key-row +8
    const int vb_row = lane & 7;
    const int vb_gsub = lane >> 4;           // dh granule +1

    #pragma unroll 1
    for (int it = 0; it < AT_NIT; it++) {
        __syncthreads();   // all warps done with stage (it-1)%3 buffers
        if (it + 2 < AT_NIT) {
            const uint32_t st = sKV + ((it + 2) % 3) * AT_KV_STG;
            #pragma unroll
            for (int i = 0; i < 4; i++) {
                uint32_t dst = st + (kv_isV[i] ? 8192u : 0u) + swz8(kv_row[i], kv_g[i]);
                const char* src = (kv_isV[i] ? Vg : Kg)
                                + (size_t)((it + 2) * 64 + kv_row[i]) * 128 + kv_g[i] * 16;
                CP_ASYNC16(dst, src);
            }
        }
        CP_COMMIT();
        CP_WAIT2();
        __syncthreads();

        if (it == 0) {
            #pragma unroll
            for (int ks = 0; ks < 4; ks++)
                LDSM4(qa[ks][0], qa[ks][1], qa[ks][2], qa[ks][3],
                      sQ + swz8(aq_row, ks * 2 + aq_kg));
        }

        const uint32_t sK = sKV + (it % 3) * AT_KV_STG;
        const uint32_t sV = sK + 8192;

        // ---- scores = Q @ K^T (exp2-domain, scale pre-folded) ----
        float sc[8][4];
        #pragma unroll
        for (int nt = 0; nt < 8; nt++)
            #pragma unroll
            for (int j = 0; j < 4; j++) sc[nt][j] = 0.f;

        #pragma unroll
        for (int ks = 0; ks < 4; ks++) {
            #pragma unroll
            for (int pr = 0; pr < 4; pr++) {
                int row = (pr * 2 + kb_sub) * 8 + kb_row;
                uint32_t b0, b1, b2, b3;
                LDSM4(b0, b1, b2, b3, sK + swz8(row, ks * 2 + kb_half));
                MMAFP16(sc[pr*2],   qa[ks][0], qa[ks][1], qa[ks][2], qa[ks][3], b0, b1);
                MMAFP16(sc[pr*2+1], qa[ks][0], qa[ks][1], qa[ks][2], qa[ks][3], b2, b3);
            }
        }

        // ---- online softmax (quad reductions) ----
        float rm0 = -1e30f, rm1 = -1e30f;
        #pragma unroll
        for (int nt = 0; nt < 8; nt++) {
            rm0 = fmaxf(rm0, fmaxf(sc[nt][0], sc[nt][1]));
            rm1 = fmaxf(rm1, fmaxf(sc[nt][2], sc[nt][3]));
        }
        rm0 = fmaxf(rm0, __shfl_xor_sync(0xffffffffu, rm0, 1));
        rm0 = fmaxf(rm0, __shfl_xor_sync(0xffffffffu, rm0, 2));
        rm1 = fmaxf(rm1, __shfl_xor_sync(0xffffffffu, rm1, 1));
        rm1 = fmaxf(rm1, __shfl_xor_sync(0xffffffffu, rm1, 2));

        float mn0 = fmaxf(mi0, rm0), mn1 = fmaxf(mi1, rm1);
        float al0 = ex2f(mi0 - mn0), al1 = ex2f(mi1 - mn1);
        mi0 = mn0; mi1 = mn1;

        float s0 = 0.f, s1 = 0.f;
        #pragma unroll
        for (int nt = 0; nt < 8; nt++) {
            sc[nt][0] = ex2f(sc[nt][0] - mn0);
            sc[nt][1] = ex2f(sc[nt][1] - mn0);
            sc[nt][2] = ex2f(sc[nt][2] - mn1);
            sc[nt][3] = ex2f(sc[nt][3] - mn1);
            s0 += sc[nt][0] + sc[nt][1];
            s1 += sc[nt][2] + sc[nt][3];
        }
        s0 += __shfl_xor_sync(0xffffffffu, s0, 1);
        s0 += __shfl_xor_sync(0xffffffffu, s0, 2);
        s1 += __shfl_xor_sync(0xffffffffu, s1, 1);
        s1 += __shfl_xor_sync(0xffffffffu, s1, 2);
        li0 = li0 * al0 + s0;
        li1 = li1 * al1 + s1;

        #pragma unroll
        for (int nt = 0; nt < 8; nt++) {
            oacc[nt][0] *= al0; oacc[nt][1] *= al0;
            oacc[nt][2] *= al1; oacc[nt][3] *= al1;
        }

        // ---- P frags from score frags (register repack) ----
        uint32_t pa[4][4];
        #pragma unroll
        for (int ks = 0; ks < 4; ks++) {
            __half2 h0 = __floats2half2_rn(sc[2*ks][0],   sc[2*ks][1]);
            __half2 h1 = __floats2half2_rn(sc[2*ks][2],   sc[2*ks][3]);
            __half2 h2 = __floats2half2_rn(sc[2*ks+1][0], sc[2*ks+1][1]);
            __half2 h3 = __floats2half2_rn(sc[2*ks+1][2], sc[2*ks+1][3]);
            pa[ks][0] = *(uint32_t*)&h0; pa[ks][1] = *(uint32_t*)&h1;
            pa[ks][2] = *(uint32_t*)&h2; pa[ks][3] = *(uint32_t*)&h3;
        }

        // ---- O += P @ V  (V b-frags via ldmatrix.trans) ----
        #pragma unroll
        for (int ks = 0; ks < 4; ks++) {
            #pragma unroll
            for (int pr = 0; pr < 4; pr++) {
                int row = ks * 16 + vb_rsub * 8 + vb_row;
                int g   = pr * 2 + vb_gsub;
                uint32_t b0, b1, b2, b3;
                LDSM4T(b0, b1, b2, b3, sV + swz8(row, g));
                MMAFP16(oacc[pr*2],   pa[ks][0], pa[ks][1], pa[ks][2], pa[ks][3], b0, b1);
                MMAFP16(oacc[pr*2+1], pa[ks][0], pa[ks][1], pa[ks][2], pa[ks][3], b2, b3);
            }
        }
    }

    // ---- epilogue: normalize, write [B,S,D] concat layout ----
    const int b = bh >> 4;
    const int h = bh & 15;
    const float inv0 = 1.0f / li0, inv1 = 1.0f / li1;
    const int m_r0 = qm0 + wrp * 16 + (lane >> 2);
    const int cbase = h * DHD + (lane & 3) * 2;
    #pragma unroll
    for (int nt = 0; nt < 8; nt++) {
        float* d0 = g_ao + ((size_t)b * SS + m_r0) * DD + cbase + nt * 8;
        *(float2*)d0 = make_float2(oacc[nt][0] * inv0, oacc[nt][1] * inv0);
        *(float2*)(d0 + 8 * DD) = make_float2(oacc[nt][2] * inv1, oacc[nt][3] * inv1);
    }
}

// ---------------------------------------------------------------------------
extern "C" void kernel_launch(void* const* d_in, const int* in_sizes, int n_in,
                              void* d_out, int out_size)
{
    const float* q  = (const float*)d_in[0];
    const float* k  = (const float*)d_in[1];
    const float* v  = (const float*)d_in[2];
    const float* Wq = (const float*)d_in[3];
    const float* Wk = (const float*)d_in[4];
    const float* Wv = (const float*)d_in[5];
    const float* Wo = (const float*)d_in[6];
    float* out = (float*)d_out;

    __nv_bfloat16 *q3, *k3, *v3, *o3, *wq3, *wk3, *wv3, *wo3;
    __half *qh16, *kh16, *vh16;
    float *ao;
    cudaGetSymbolAddress((void**)&q3,  g_q3);
    cudaGetSymbolAddress((void**)&k3,  g_k3);
    cudaGetSymbolAddress((void**)&v3,  g_v3);
    cudaGetSymbolAddress((void**)&o3,  g_o3);
    cudaGetSymbolAddress((void**)&wq3, g_wq3);
    cudaGetSymbolAddress((void**)&wk3, g_wk3);
    cudaGetSymbolAddress((void**)&wv3, g_wv3);
    cudaGetSymbolAddress((void**)&wo3, g_wo3);
    cudaGetSymbolAddress((void**)&qh16, g_qh16);
    cudaGetSymbolAddress((void**)&kh16, g_kh16);
    cudaGetSymbolAddress((void**)&vh16, g_vh16);
    cudaGetSymbolAddress((void**)&ao,  g_ao);

    cudaFuncSetAttribute(gemm_mma, cudaFuncAttributeMaxDynamicSharedMemorySize, GEMM_SMEM);
    cudaFuncSetAttribute(attn_mma, cudaFuncAttributeMaxDynamicSharedMemorySize, ATTN_SMEM);

    // split fp32 -> stacked bf16
    split3<<<MM, 256>>>((const float4*)q,  q3, 1);
    split3<<<MM, 256>>>((const float4*)k,  k3, 1);
    split3<<<MM, 256>>>((const float4*)v,  v3, 1);
    split3<<<DD, 256>>>((const float4*)Wq, wq3, 0);
    split3<<<DD, 256>>>((const float4*)Wk, wk3, 0);
    split3<<<DD, 256>>>((const float4*)Wv, wv3, 0);
    split3<<<DD, 256>>>((const float4*)Wo, wo3, 0);

    // projections -> fp16 head layout (Q pre-scaled by 0.125*log2(e))
    dim3 gg(DD / NB, MM / MB);
    const float qscale = 0.125f * 1.44269504f;
    gemm_mma<<<gg, 256, GEMM_SMEM>>>(q3, wq3, nullptr, qh16, qscale, 1);
    gemm_mma<<<gg, 256, GEMM_SMEM>>>(k3, wk3, nullptr, kh16, 1.0f, 1);
    gemm_mma<<<gg, 256, GEMM_SMEM>>>(v3, wv3, nullptr, vh16, 1.0f, 1);

    // tensor-core flash attention
    dim3 ga(SS / 128, BB * HH);
    attn_mma<<<ga, 256, ATTN_SMEM>>>();

    // output projection (f32 out)
    split3<<<MM, 256>>>((const float4*)ao, o3, 1);
    gemm_mma<<<gg, 256, GEMM_SMEM>>>(o3, wo3, out, nullptr, 1.0f, 0);
}

// round 7
// speedup vs baseline: 4.0674x; 1.2002x over previous
#include <cuda_runtime.h>
#include <cuda_bf16.h>
#include <cuda_fp16.h>
#include <cstdint>
#include <math.h>

// ---------------- problem constants ----------------
#define BB 2
#define SS 2048
#define DD 1024
#define HH 16
#define DHD 64
#define MM (BB*SS)      // 4096

// ---------------- split-bf16 GEMM constants (verified R4 config) -----------
#define KTOT 3072
#define MB 128
#define NB 128
#define KC 32
#define NCHUNK (KTOT/KC)        // 96
#define NSTG 4
#define A_STG 8192
#define B_STG 8192
#define STG_BYTES (A_STG+B_STG)
#define GEMM_SMEM (NSTG*STG_BYTES)  // 65536

// ---------------- scratch ----------------
__device__ float g_ao[MM*DD];
__device__ __half g_qh16[BB*HH*SS*DHD];
__device__ __half g_kh16[BB*HH*SS*DHD];
__device__ __half g_vh16[BB*HH*SS*DHD];

__device__ __nv_bfloat16 g_q3[(size_t)MM*KTOT];
__device__ __nv_bfloat16 g_k3[(size_t)MM*KTOT];
__device__ __nv_bfloat16 g_v3[(size_t)MM*KTOT];
__device__ __nv_bfloat16 g_o3[(size_t)MM*KTOT];
__device__ __nv_bfloat16 g_wq3[(size_t)DD*KTOT];
__device__ __nv_bfloat16 g_wk3[(size_t)DD*KTOT];
__device__ __nv_bfloat16 g_wv3[(size_t)DD*KTOT];
__device__ __nv_bfloat16 g_wo3[(size_t)DD*KTOT];

// ---------------- PTX helpers ----------------
__device__ __forceinline__ uint32_t smem_u32(const void* p) {
    uint32_t a;
    asm("{ .reg .u64 t; cvta.to.shared.u64 t, %1; cvt.u32.u64 %0, t; }"
        : "=r"(a) : "l"(p));
    return a;
}

#define CP_ASYNC16(dst, src) \
    asm volatile("cp.async.cg.shared.global [%0], [%1], 16;" :: "r"(dst), "l"(src))
#define CP_COMMIT() asm volatile("cp.async.commit_group;" ::: "memory")
#define CP_WAIT2()  asm volatile("cp.async.wait_group 2;" ::: "memory")

#define LDSM4(r0, r1, r2, r3, addr) \
    asm volatile("ldmatrix.sync.aligned.m8n8.x4.shared.b16 {%0,%1,%2,%3}, [%4];" \
        : "=r"(r0), "=r"(r1), "=r"(r2), "=r"(r3) : "r"(addr))
#define LDSM4T(r0, r1, r2, r3, addr) \
    asm volatile("ldmatrix.sync.aligned.m8n8.x4.trans.shared.b16 {%0,%1,%2,%3}, [%4];" \
        : "=r"(r0), "=r"(r1), "=r"(r2), "=r"(r3) : "r"(addr))

#define MMABF(c, a, b) \
    asm volatile("mma.sync.aligned.m16n8k16.row.col.f32.bf16.bf16.f32 " \
        "{%0,%1,%2,%3}, {%4,%5,%6,%7}, {%8,%9}, {%0,%1,%2,%3};" \
        : "+f"((c)[0]), "+f"((c)[1]), "+f"((c)[2]), "+f"((c)[3]) \
        : "r"((a)[0]), "r"((a)[1]), "r"((a)[2]), "r"((a)[3]), \
          "r"((b)[0]), "r"((b)[1]))

#define MMAFP16(c, a0, a1, a2, a3, b0, b1) \
    asm volatile("mma.sync.aligned.m16n8k16.row.col.f32.f16.f16.f32 " \
        "{%0,%1,%2,%3}, {%4,%5,%6,%7}, {%8,%9}, {%0,%1,%2,%3};" \
        : "+f"((c)[0]), "+f"((c)[1]), "+f"((c)[2]), "+f"((c)[3]) \
        : "r"(a0), "r"(a1), "r"(a2), "r"(a3), "r"(b0), "r"(b1))

__device__ __forceinline__ float ex2f(float x) {
    float y; asm("ex2.approx.f32 %0, %1;" : "=f"(y) : "f"(x)); return y;
}

// swizzle for 64B rows (gemm tiles) — verified
__device__ __forceinline__ uint32_t swz(int row, int g) {
    return (uint32_t)(row * 64 + ((g ^ ((row >> 1) & 3)) * 16));
}
// swizzle for 128B rows (attention tiles) — verified
__device__ __forceinline__ uint32_t swz8(int row, int g) {
    return (uint32_t)(row * 128 + ((g ^ (row & 7)) << 4));
}

// ---------------------------------------------------------------------------
// split3: fp32 [rows,1024] -> stacked bf16 [rows,3072]
//   act==1: [hi|lo|hi]  act==0: [hi|hi|lo]
// ---------------------------------------------------------------------------
__device__ __forceinline__ void split3_body(const float4* __restrict__ X,
                                            __nv_bfloat16* __restrict__ Y,
                                            int act, int e)
{
    int row = e >> 8;
    int c4  = e & 255;
    float4 x = X[e];

    __nv_bfloat162 ha = __floats2bfloat162_rn(x.x, x.y);
    __nv_bfloat162 hb = __floats2bfloat162_rn(x.z, x.w);
    __nv_bfloat162 la = __floats2bfloat162_rn(x.x - __low2float(ha), x.y - __high2float(ha));
    __nv_bfloat162 lb = __floats2bfloat162_rn(x.z - __low2float(hb), x.w - __high2float(hb));

    __nv_bfloat162* y  = (__nv_bfloat162*)(Y + (size_t)row * KTOT + c4 * 4);
    __nv_bfloat162* y1 = y + 512;
    __nv_bfloat162* y2 = y + 1024;
    y[0] = ha; y[1] = hb;
    if (act) { y1[0] = la; y1[1] = lb; y2[0] = ha; y2[1] = hb; }
    else     { y1[0] = ha; y1[1] = hb; y2[0] = la; y2[1] = lb; }
}

__global__ void __launch_bounds__(256) split3(const float4* __restrict__ X,
                                              __nv_bfloat16* __restrict__ Y, int act)
{
    split3_body(X, Y, act, blockIdx.x * 256 + threadIdx.x);
}

// fused triple split (activations q,k,v)
__global__ void __launch_bounds__(256) split3x(const float4* X0, const float4* X1,
                                               const float4* X2,
                                               __nv_bfloat16* Y0, __nv_bfloat16* Y1,
                                               __nv_bfloat16* Y2, int act)
{
    const float4* X = (blockIdx.y == 0) ? X0 : (blockIdx.y == 1) ? X1 : X2;
    __nv_bfloat16* Y = (blockIdx.y == 0) ? Y0 : (blockIdx.y == 1) ? Y1 : Y2;
    split3_body(X, Y, act, blockIdx.x * 256 + threadIdx.x);
}

// fused quad split (weights Wq,Wk,Wv,Wo)  — THE R5/R6 BUG FIX: Wo included
__global__ void __launch_bounds__(256) split3w(const float4* X0, const float4* X1,
                                               const float4* X2, const float4* X3,
                                               __nv_bfloat16* Y0, __nv_bfloat16* Y1,
                                               __nv_bfloat16* Y2, __nv_bfloat16* Y3)
{
    const float4* X = (blockIdx.y == 0) ? X0 : (blockIdx.y == 1) ? X1
                     : (blockIdx.y == 2) ? X2 : X3;
    __nv_bfloat16* Y = (blockIdx.y == 0) ? Y0 : (blockIdx.y == 1) ? Y1
                     : (blockIdx.y == 2) ? Y2 : Y3;
    split3_body(X, Y, 0, blockIdx.x * 256 + threadIdx.x);
}

// ---------------------------------------------------------------------------
// VERIFIED R4 GEMM inner machinery (byte-identical core).
// CTA 128x128, 8 warps (2M x 4N), warp tile 64x32, KC=32, 4 stages.
// ---------------------------------------------------------------------------
__device__ __forceinline__ void gemm_core(const __nv_bfloat16* __restrict__ A3,
                                          const __nv_bfloat16* __restrict__ W3,
                                          int bm, int bn, uint32_t sb,
                                          float cfr[4][4][4])
{
    const int tid  = threadIdx.x;
    const int lane = tid & 31;
    const int wid  = tid >> 5;
    const int wm   = (wid & 1) * 64;
    const int wn   = (wid >> 1) * 32;

    const char* gA = (const char*)(A3 + (size_t)bm * KTOT);
    const char* gB = (const char*)(W3 + (size_t)bn * KTOT);

    #pragma unroll
    for (int i = 0; i < 4; i++)
        #pragma unroll
        for (int j = 0; j < 4; j++)
            #pragma unroll
            for (int e = 0; e < 4; e++) cfr[i][j][e] = 0.f;

    int l_isB[4];
    uint32_t l_soff[4];
    size_t l_goff[4];
    #pragma unroll
    for (int i = 0; i < 4; i++) {
        int G = tid + i * 256;
        l_isB[i] = G >> 9;
        int g = G & 511;
        int row = g >> 2;
        int q = g & 3;
        l_soff[i] = (l_isB[i] ? A_STG : 0u) + swz(row, q);
        l_goff[i] = (size_t)row * (KTOT * 2) + q * 16;
    }

    #pragma unroll
    for (int s = 0; s < NSTG - 1; s++) {
        const uint32_t st = sb + s * STG_BYTES;
        #pragma unroll
        for (int i = 0; i < 4; i++) {
            const char* src = (l_isB[i] ? gB : gA) + l_goff[i] + (size_t)s * (KC * 2);
            CP_ASYNC16(st + l_soff[i], src);
        }
        CP_COMMIT();
    }

    const int a_row = lane & 15;
    const int a_kg  = lane >> 4;
    const int b_j   = lane >> 4;
    const int b_half= (lane >> 3) & 1;
    const int b_row = lane & 7;

    #pragma unroll 1
    for (int c = 0; c < NCHUNK; c++) {
        CP_WAIT2();
        __syncthreads();

        if (c + NSTG - 1 < NCHUNK) {
            const uint32_t st = sb + ((c + NSTG - 1) & (NSTG - 1)) * STG_BYTES;
            #pragma unroll
            for (int i = 0; i < 4; i++) {
                const char* src = (l_isB[i] ? gB : gA) + l_goff[i]
                                + (size_t)(c + NSTG - 1) * (KC * 2);
                CP_ASYNC16(st + l_soff[i], src);
            }
        }
        CP_COMMIT();

        const uint32_t sA = sb + (c & (NSTG - 1)) * STG_BYTES;
        const uint32_t sBs = sA + A_STG;

        #pragma unroll
        for (int ks = 0; ks < 2; ks++) {
            uint32_t a[4][4];
            #pragma unroll
            for (int mt = 0; mt < 4; mt++) {
                int row = wm + mt * 16 + a_row;
                int kg  = ks * 2 + a_kg;
                LDSM4(a[mt][0], a[mt][1], a[mt][2], a[mt][3], sA + swz(row, kg));
            }
            uint32_t b[4][2];
            #pragma unroll
            for (int pr = 0; pr < 2; pr++) {
                int row = wn + (pr * 2 + b_j) * 8 + b_row;
                int kg  = ks * 2 + b_half;
                uint32_t r0, r1, r2, r3;
                LDSM4(r0, r1, r2, r3, sBs + swz(row, kg));
                b[pr*2][0] = r0; b[pr*2][1] = r1;
                b[pr*2+1][0] = r2; b[pr*2+1][1] = r3;
            }
            #pragma unroll
            for (int mt = 0; mt < 4; mt++)
                #pragma unroll
                for (int nt = 0; nt < 4; nt++)
                    MMABF(cfr[mt][nt], a[mt], b[nt]);
        }
        __syncthreads();
    }
}

// Fused QKV projection: seg = blockIdx.x>>3 selects (A,W,out,scale).
__global__ void __launch_bounds__(256) gemm_qkv(
    const __nv_bfloat16* __restrict__ A0, const __nv_bfloat16* __restrict__ A1,
    const __nv_bfloat16* __restrict__ A2,
    const __nv_bfloat16* __restrict__ W0, const __nv_bfloat16* __restrict__ W1,
    const __nv_bfloat16* __restrict__ W2,
    __half* __restrict__ H0, __half* __restrict__ H1, __half* __restrict__ H2,
    float qscale)
{
    extern __shared__ char dsm[];
    const uint32_t sb = smem_u32(dsm);

    const int seg = blockIdx.x >> 3;
    const int bn  = (blockIdx.x & 7) * NB;
    const int bm  = blockIdx.y * MB;

    const __nv_bfloat16* A3 = (seg == 0) ? A0 : (seg == 1) ? A1 : A2;
    const __nv_bfloat16* W3 = (seg == 0) ? W0 : (seg == 1) ? W1 : W2;
    __half* Hout            = (seg == 0) ? H0 : (seg == 1) ? H1 : H2;
    const float scale = (seg == 0) ? qscale : 1.0f;

    float cfr[4][4][4];
    gemm_core(A3, W3, bm, bn, sb, cfr);

    const int lane = threadIdx.x & 31;
    const int wid  = threadIdx.x >> 5;
    const int wm   = (wid & 1) * 64;
    const int wn   = (wid >> 1) * 32;
    const int r0   = lane >> 2;
    const int cc0  = (lane & 3) * 2;
    #pragma unroll
    for (int mt = 0; mt < 4; mt++) {
        #pragma unroll
        for (int nt = 0; nt < 4; nt++) {
            int m = bm + wm + mt * 16 + r0;
            int n = bn + wn + nt * 8 + cc0;
            int bb = m >> 11, s = m & 2047, h = n >> 6, dh = n & 63;
            __half* d0 = Hout + (((size_t)(bb * HH + h) * SS + s) * DHD + dh);
            *(__half2*)d0 = __floats2half2_rn(cfr[mt][nt][0]*scale, cfr[mt][nt][1]*scale);
            *(__half2*)(d0 + 8 * DHD) = __floats2half2_rn(cfr[mt][nt][2]*scale, cfr[mt][nt][3]*scale);
        }
    }
}

// O-projection: flat f32 out.
__global__ void __launch_bounds__(256) gemm_out(const __nv_bfloat16* __restrict__ A3,
                                                const __nv_bfloat16* __restrict__ W3,
                                                float* __restrict__ f32dst)
{
    extern __shared__ char dsm[];
    const uint32_t sb = smem_u32(dsm);

    const int bn = blockIdx.x * NB;
    const int bm = blockIdx.y * MB;

    float cfr[4][4][4];
    gemm_core(A3, W3, bm, bn, sb, cfr);

    const int lane = threadIdx.x & 31;
    const int wid  = threadIdx.x >> 5;
    const int wm   = (wid & 1) * 64;
    const int wn   = (wid >> 1) * 32;
    const int r0   = lane >> 2;
    const int cc0  = (lane & 3) * 2;
    #pragma unroll
    for (int mt = 0; mt < 4; mt++) {
        #pragma unroll
        for (int nt = 0; nt < 4; nt++) {
            int m = bm + wm + mt * 16 + r0;
            int n = bn + wn + nt * 8 + cc0;
            float* d0 = f32dst + (size_t)m * DD + n;
            *(float2*)d0 = make_float2(cfr[mt][nt][0], cfr[mt][nt][1]);
            *(float2*)(d0 + 8 * DD) = make_float2(cfr[mt][nt][2], cfr[mt][nt][3]);
        }
    }
}

// ---------------------------------------------------------------------------
// Tensor-core flash attention — unchanged verified R4 kernel
// ---------------------------------------------------------------------------
#define AT_NIT (SS/64)
#define AT_KV_STG 16384
#define ATTN_SMEM (16384 + 3*AT_KV_STG)   // 65536

__global__ void __launch_bounds__(256) attn_mma()
{
    extern __shared__ char smA[];
    const uint32_t sQ  = smem_u32(smA);
    const uint32_t sKV = sQ + 16384;

    const int tid  = threadIdx.x;
    const int lane = tid & 31;
    const int wrp  = tid >> 5;
    const int bh   = blockIdx.y;
    const int qm0  = blockIdx.x * 128;

    const char* Qg = (const char*)g_qh16 + ((size_t)bh * SS + qm0) * 128;
    const char* Kg = (const char*)g_kh16 + (size_t)bh * SS * 128;
    const char* Vg = (const char*)g_vh16 + (size_t)bh * SS * 128;

    int kv_isV[4], kv_row[4], kv_g[4];
    #pragma unroll
    for (int i = 0; i < 4; i++) {
        int G = tid + i * 256;
        kv_isV[i] = G >> 9;
        int g = G & 511;
        kv_row[i] = g >> 3;
        kv_g[i]   = g & 7;
    }

    #pragma unroll
    for (int i = 0; i < 4; i++) {
        int G = tid + i * 256;
        int r = G >> 3, g = G & 7;
        CP_ASYNC16(sQ + swz8(r, g), Qg + r * 128 + g * 16);
    }
    #pragma unroll
    for (int i = 0; i < 4; i++) {
        uint32_t dst = sKV + (kv_isV[i] ? 8192u : 0u) + swz8(kv_row[i], kv_g[i]);
        const char* src = (kv_isV[i] ? Vg : Kg) + (size_t)kv_row[i] * 128 + kv_g[i] * 16;
        CP_ASYNC16(dst, src);
    }
    CP_COMMIT();
    #pragma unroll
    for (int i = 0; i < 4; i++) {
        uint32_t dst = sKV + AT_KV_STG + (kv_isV[i] ? 8192u : 0u) + swz8(kv_row[i], kv_g[i]);
        const char* src = (kv_isV[i] ? Vg : Kg) + (size_t)(64 + kv_row[i]) * 128 + kv_g[i] * 16;
        CP_ASYNC16(dst, src);
    }
    CP_COMMIT();

    uint32_t qa[4][4];
    float oacc[8][4];
    #pragma unroll
    for (int nt = 0; nt < 8; nt++)
        #pragma unroll
        for (int j = 0; j < 4; j++) oacc[nt][j] = 0.f;
    float mi0 = -1e30f, mi1 = -1e30f, li0 = 0.f, li1 = 0.f;

    const int aq_row = wrp * 16 + (lane & 15);
    const int aq_kg  = lane >> 4;
    const int kb_sub = lane >> 4;
    const int kb_half = (lane >> 3) & 1;
    const int kb_row = lane & 7;
    const int vb_rsub = (lane >> 3) & 1;
    const int vb_row = lane & 7;
    const int vb_gsub = lane >> 4;

    #pragma unroll 1
    for (int it = 0; it < AT_NIT; it++) {
        __syncthreads();
        if (it + 2 < AT_NIT) {
            const uint32_t st = sKV + ((it + 2) % 3) * AT_KV_STG;
            #pragma unroll
            for (int i = 0; i < 4; i++) {
                uint32_t dst = st + (kv_isV[i] ? 8192u : 0u) + swz8(kv_row[i], kv_g[i]);
                const char* src = (kv_isV[i] ? Vg : Kg)
                                + (size_t)((it + 2) * 64 + kv_row[i]) * 128 + kv_g[i] * 16;
                CP_ASYNC16(dst, src);
            }
        }
        CP_COMMIT();
        CP_WAIT2();
        __syncthreads();

        if (it == 0) {
            #pragma unroll
            for (int ks = 0; ks < 4; ks++)
                LDSM4(qa[ks][0], qa[ks][1], qa[ks][2], qa[ks][3],
                      sQ + swz8(aq_row, ks * 2 + aq_kg));
        }

        const uint32_t sK = sKV + (it % 3) * AT_KV_STG;
        const uint32_t sV = sK + 8192;

        float sc[8][4];
        #pragma unroll
        for (int nt = 0; nt < 8; nt++)
            #pragma unroll
            for (int j = 0; j < 4; j++) sc[nt][j] = 0.f;

        #pragma unroll
        for (int ks = 0; ks < 4; ks++) {
            #pragma unroll
            for (int pr = 0; pr < 4; pr++) {
                int row = (pr * 2 + kb_sub) * 8 + kb_row;
                uint32_t b0, b1, b2, b3;
                LDSM4(b0, b1, b2, b3, sK + swz8(row, ks * 2 + kb_half));
                MMAFP16(sc[pr*2],   qa[ks][0], qa[ks][1], qa[ks][2], qa[ks][3], b0, b1);
                MMAFP16(sc[pr*2+1], qa[ks][0], qa[ks][1], qa[ks][2], qa[ks][3], b2, b3);
            }
        }

        float rm0 = -1e30f, rm1 = -1e30f;
        #pragma unroll
        for (int nt = 0; nt < 8; nt++) {
            rm0 = fmaxf(rm0, fmaxf(sc[nt][0], sc[nt][1]));
            rm1 = fmaxf(rm1, fmaxf(sc[nt][2], sc[nt][3]));
        }
        rm0 = fmaxf(rm0, __shfl_xor_sync(0xffffffffu, rm0, 1));
        rm0 = fmaxf(rm0, __shfl_xor_sync(0xffffffffu, rm0, 2));
        rm1 = fmaxf(rm1, __shfl_xor_sync(0xffffffffu, rm1, 1));
        rm1 = fmaxf(rm1, __shfl_xor_sync(0xffffffffu, rm1, 2));

        float mn0 = fmaxf(mi0, rm0), mn1 = fmaxf(mi1, rm1);
        float al0 = ex2f(mi0 - mn0), al1 = ex2f(mi1 - mn1);
        mi0 = mn0; mi1 = mn1;

        float s0 = 0.f, s1 = 0.f;
        #pragma unroll
        for (int nt = 0; nt < 8; nt++) {
            sc[nt][0] = ex2f(sc[nt][0] - mn0);
            sc[nt][1] = ex2f(sc[nt][1] - mn0);
            sc[nt][2] = ex2f(sc[nt][2] - mn1);
            sc[nt][3] = ex2f(sc[nt][3] - mn1);
            s0 += sc[nt][0] + sc[nt][1];
            s1 += sc[nt][2] + sc[nt][3];
        }
        s0 += __shfl_xor_sync(0xffffffffu, s0, 1);
        s0 += __shfl_xor_sync(0xffffffffu, s0, 2);
        s1 += __shfl_xor_sync(0xffffffffu, s1, 1);
        s1 += __shfl_xor_sync(0xffffffffu, s1, 2);
        li0 = li0 * al0 + s0;
        li1 = li1 * al1 + s1;

        #pragma unroll
        for (int nt = 0; nt < 8; nt++) {
            oacc[nt][0] *= al0; oacc[nt][1] *= al0;
            oacc[nt][2] *= al1; oacc[nt][3] *= al1;
        }

        uint32_t pa[4][4];
        #pragma unroll
        for (int ks = 0; ks < 4; ks++) {
            __half2 h0 = __floats2half2_rn(sc[2*ks][0],   sc[2*ks][1]);
            __half2 h1 = __floats2half2_rn(sc[2*ks][2],   sc[2*ks][3]);
            __half2 h2 = __floats2half2_rn(sc[2*ks+1][0], sc[2*ks+1][1]);
            __half2 h3 = __floats2half2_rn(sc[2*ks+1][2], sc[2*ks+1][3]);
            pa[ks][0] = *(uint32_t*)&h0; pa[ks][1] = *(uint32_t*)&h1;
            pa[ks][2] = *(uint32_t*)&h2; pa[ks][3] = *(uint32_t*)&h3;
        }

        #pragma unroll
        for (int ks = 0; ks < 4; ks++) {
            #pragma unroll
            for (int pr = 0; pr < 4; pr++) {
                int row = ks * 16 + vb_rsub * 8 + vb_row;
                int g   = pr * 2 + vb_gsub;
                uint32_t b0, b1, b2, b3;
                LDSM4T(b0, b1, b2, b3, sV + swz8(row, g));
                MMAFP16(oacc[pr*2],   pa[ks][0], pa[ks][1], pa[ks][2], pa[ks][3], b0, b1);
                MMAFP16(oacc[pr*2+1], pa[ks][0], pa[ks][1], pa[ks][2], pa[ks][3], b2, b3);
            }
        }
    }

    const int b = bh >> 4;
    const int h = bh & 15;
    const float inv0 = 1.0f / li0, inv1 = 1.0f / li1;
    const int m_r0 = qm0 + wrp * 16 + (lane >> 2);
    const int cbase = h * DHD + (lane & 3) * 2;
    #pragma unroll
    for (int nt = 0; nt < 8; nt++) {
        float* d0 = g_ao + ((size_t)b * SS + m_r0) * DD + cbase + nt * 8;
        *(float2*)d0 = make_float2(oacc[nt][0] * inv0, oacc[nt][1] * inv0);
        *(float2*)(d0 + 8 * DD) = make_float2(oacc[nt][2] * inv1, oacc[nt][3] * inv1);
    }
}

// ---------------------------------------------------------------------------
extern "C" void kernel_launch(void* const* d_in, const int* in_sizes, int n_in,
                              void* d_out, int out_size)
{
    const float* q  = (const float*)d_in[0];
    const float* k  = (const float*)d_in[1];
    const float* v  = (const float*)d_in[2];
    const float* Wq = (const float*)d_in[3];
    const float* Wk = (const float*)d_in[4];
    const float* Wv = (const float*)d_in[5];
    const float* Wo = (const float*)d_in[6];
    float* out = (float*)d_out;

    __nv_bfloat16 *q3, *k3, *v3, *o3, *wq3, *wk3, *wv3, *wo3;
    __half *qh16, *kh16, *vh16;
    float *ao;
    cudaGetSymbolAddress((void**)&q3,  g_q3);
    cudaGetSymbolAddress((void**)&k3,  g_k3);
    cudaGetSymbolAddress((void**)&v3,  g_v3);
    cudaGetSymbolAddress((void**)&o3,  g_o3);
    cudaGetSymbolAddress((void**)&wq3, g_wq3);
    cudaGetSymbolAddress((void**)&wk3, g_wk3);
    cudaGetSymbolAddress((void**)&wv3, g_wv3);
    cudaGetSymbolAddress((void**)&wo3, g_wo3);
    cudaGetSymbolAddress((void**)&qh16, g_qh16);
    cudaGetSymbolAddress((void**)&kh16, g_kh16);
    cudaGetSymbolAddress((void**)&vh16, g_vh16);
    cudaGetSymbolAddress((void**)&ao,  g_ao);

    cudaFuncSetAttribute(gemm_qkv, cudaFuncAttributeMaxDynamicSharedMemorySize, GEMM_SMEM);
    cudaFuncSetAttribute(gemm_out, cudaFuncAttributeMaxDynamicSharedMemorySize, GEMM_SMEM);
    cudaFuncSetAttribute(attn_mma, cudaFuncAttributeMaxDynamicSharedMemorySize, ATTN_SMEM);

    // fused splits: activations (q,k,v); weights (Wq,Wk,Wv,Wo) — Wo FIXED IN
    dim3 sa(MM, 3), sw(DD, 4);
    split3x<<<sa, 256>>>((const float4*)q, (const float4*)k, (const float4*)v,
                         q3, k3, v3, 1);
    split3w<<<sw, 256>>>((const float4*)Wq, (const float4*)Wk,
                         (const float4*)Wv, (const float4*)Wo,
                         wq3, wk3, wv3, wo3);

    // fused QKV projection -> fp16 head layout (Q pre-scaled by 0.125*log2 e)
    const float qscale = 0.125f * 1.44269504f;
    dim3 gqkv(24, MM / MB);    // 24 = 3 segs x 8 N-tiles; 32 M-tiles
    gemm_qkv<<<gqkv, 256, GEMM_SMEM>>>(q3, k3, v3, wq3, wk3, wv3,
                                       qh16, kh16, vh16, qscale);

    // tensor-core flash attention
    dim3 ga(SS / 128, BB * HH);
    attn_mma<<<ga, 256, ATTN_SMEM>>>();

    // output projection
    split3<<<MM, 256>>>((const float4*)ao, o3, 1);
    dim3 go(DD / NB, MM / MB);
    gemm_out<<<go, 256, GEMM_SMEM>>>(o3, wo3, out);
}